// round 11
// baseline (speedup 1.0000x reference)
#include <cuda_runtime.h>
#include <cuda_bf16.h>
#include <math.h>
#include <stdint.h>

#define BCNT  4
#define SEQ   1024
#define EMB   512
#define NH    8
#define HD    64
#define MROWS 4096
#define TMAXS 20

// scratch (static device globals; allocation-free per harness rules)
__device__ __nv_bfloat16 g_qb[MROWS * EMB];   // spike counts (exact ints in bf16)
__device__ __nv_bfloat16 g_kb[MROWS * EMB];
__device__ __nv_bfloat16 g_vb[MROWS * EMB];   // RAW spike counts (no /20)
__device__ int   g_T[MROWS];

// 3-way bf16 splits for proj only (A = attention output, W = Wo)
__device__ __nv_bfloat16 gWo0[EMB * EMB], gWo1[EMB * EMB], gWo2[EMB * EMB];
__device__ __nv_bfloat16 gA0[MROWS * EMB], gA1[MROWS * EMB], gA2[MROWS * EMB];

// ===========================================================================
// PTX helpers (baseline PTX only)
// ===========================================================================
__device__ __forceinline__ uint32_t smem_u32(const void* p) {
    uint32_t a;
    asm("{ .reg .u64 t; cvta.to.shared.u64 t, %1; cvt.u32.u64 %0, t; }" : "=r"(a) : "l"(p));
    return a;
}

#define CP_ASYNC16(dst, src) \
    asm volatile("cp.async.cg.shared.global [%0], [%1], 16;" :: "r"(dst), "l"(src))
#define CP_COMMIT() asm volatile("cp.async.commit_group;" ::: "memory")
#define CP_WAIT(n)  asm volatile("cp.async.wait_group %0;" :: "n"(n) : "memory")

#define LDMATRIX_X2(r0, r1, addr) \
    asm volatile("ldmatrix.sync.aligned.m8n8.x2.shared.b16 {%0,%1}, [%2];" \
                 : "=r"(r0), "=r"(r1) : "r"(addr))
#define LDMATRIX_X2_T(r0, r1, addr) \
    asm volatile("ldmatrix.sync.aligned.m8n8.x2.trans.shared.b16 {%0,%1}, [%2];" \
                 : "=r"(r0), "=r"(r1) : "r"(addr))
#define LDMATRIX_X4(r0, r1, r2, r3, addr) \
    asm volatile("ldmatrix.sync.aligned.m8n8.x4.shared.b16 {%0,%1,%2,%3}, [%4];" \
                 : "=r"(r0), "=r"(r1), "=r"(r2), "=r"(r3) : "r"(addr))

#define MMA_BF16(d, a, b0, b1) \
    asm volatile("mma.sync.aligned.m16n8k16.row.col.f32.bf16.bf16.f32 " \
                 "{%0,%1,%2,%3}, {%4,%5,%6,%7}, {%8,%9}, {%0,%1,%2,%3};" \
                 : "+f"((d)[0]), "+f"((d)[1]), "+f"((d)[2]), "+f"((d)[3]) \
                 : "r"((a)[0]), "r"((a)[1]), "r"((a)[2]), "r"((a)[3]), \
                   "r"(b0), "r"(b1))

__device__ __forceinline__ uint32_t pack_bf2(float lo, float hi) {
    __nv_bfloat162 v = __floats2bfloat162_rn(lo, hi);
    return *(uint32_t*)&v;
}
__device__ __forceinline__ uint32_t pack2b(__nv_bfloat16 a, __nv_bfloat16 b) {
    return ((uint32_t)__bfloat16_as_ushort(b) << 16) | (uint32_t)__bfloat16_as_ushort(a);
}
__device__ __forceinline__ void split3(float v, __nv_bfloat16& b0, __nv_bfloat16& b1,
                                       __nv_bfloat16& b2) {
    b0 = __float2bfloat16(v);
    float r = v - __bfloat162float(b0);
    b1 = __float2bfloat16(r);
    float r2 = r - __bfloat162float(b1);
    b2 = __float2bfloat16(r2);
}

// packed fp32x2 FMA (each lane = IEEE fp32 fma.rn — fp32-exact semantics)
__device__ __forceinline__ void fma2(uint64_t& c, uint64_t a, uint64_t b) {
    asm("fma.rn.f32x2 %0, %1, %2, %0;" : "+l"(c) : "l"(a), "l"(b));
}
__device__ __forceinline__ uint64_t dup2(float x) {
    uint64_t r;
    asm("mov.b64 %0, {%1, %1};" : "=l"(r) : "f"(x));
    return r;
}
__device__ __forceinline__ void unpack2(uint64_t v, float& lo, float& hi) {
    asm("mov.b64 {%0, %1}, %2;" : "=f"(lo), "=f"(hi) : "l"(v));
}

// ===========================================================================
// split Wo (proj B operand) -> 3 bf16 terms
// ===========================================================================
__global__ __launch_bounds__(256) void split_wo_kernel(const float* __restrict__ Wo)
{
    const int base = (blockIdx.x * 256 + threadIdx.x) * 4;
    float4 v = *(const float4*)(Wo + base);
    __nv_bfloat16 a0, a1, a2, b0, b1, b2, c0, c1, c2, d0, d1, d2;
    split3(v.x, a0, a1, a2);
    split3(v.y, b0, b1, b2);
    split3(v.z, c0, c1, c2);
    split3(v.w, d0, d1, d2);
    *(uint2*)(gWo0 + base) = make_uint2(pack2b(a0, b0), pack2b(c0, d0));
    *(uint2*)(gWo1 + base) = make_uint2(pack2b(a1, b1), pack2b(c1, d1));
    *(uint2*)(gWo2 + base) = make_uint2(pack2b(a2, b2), pack2b(c2, d2));
}

// ===========================================================================
// Kernel A: gate + complexity MLPs -> adaptive window T_i (unchanged)
// ===========================================================================
__global__ __launch_bounds__(128) void gate_kernel(
    const float* __restrict__ x,
    const float* __restrict__ gW1, const float* __restrict__ gb1,
    const float* __restrict__ gg,  const float* __restrict__ gbe,
    const float* __restrict__ gW2, const float* __restrict__ gb2,
    const float* __restrict__ gW3, const float* __restrict__ gb3,
    const float* __restrict__ cW1, const float* __restrict__ cb1,
    const float* __restrict__ cg,  const float* __restrict__ cbe,
    const float* __restrict__ cW2, const float* __restrict__ cb2,
    const float* __restrict__ cW3, const float* __restrict__ cb3)
{
    __shared__ float xs[8][EMB];
    __shared__ float h1[8][128];
    __shared__ float h2[8][64];
    __shared__ float h1c[8][64];
    __shared__ float h2c[8][32];
    __shared__ float stat[8][2];
    __shared__ float gsc[8], csc[8];

    const int tid  = threadIdx.x;
    const int wid  = tid >> 5, lane = tid & 31;
    const int row0 = blockIdx.x * 8;

    for (int i = tid; i < 8 * EMB; i += 128)
        xs[i >> 9][i & 511] = x[row0 * EMB + i];
    __syncthreads();

    {
        float acc[8];
        float bvv = gb1[tid];
        #pragma unroll
        for (int r = 0; r < 8; r++) acc[r] = bvv;
        for (int e = 0; e < EMB; e++) {
            float w = gW1[e * 128 + tid];
            #pragma unroll
            for (int r = 0; r < 8; r++) acc[r] = fmaf(xs[r][e], w, acc[r]);
        }
        #pragma unroll
        for (int r = 0; r < 8; r++) h1[r][tid] = acc[r];
    }
    __syncthreads();
    for (int r = wid * 2; r < wid * 2 + 2; r++) {
        float v0 = h1[r][lane], v1 = h1[r][lane + 32], v2 = h1[r][lane + 64], v3 = h1[r][lane + 96];
        float s = v0 + v1 + v2 + v3;
        float ss = v0 * v0 + v1 * v1 + v2 * v2 + v3 * v3;
        #pragma unroll
        for (int o = 16; o >= 1; o >>= 1) {
            s  += __shfl_xor_sync(0xffffffffu, s, o);
            ss += __shfl_xor_sync(0xffffffffu, ss, o);
        }
        if (lane == 0) {
            float mu = s / 128.f;
            stat[r][0] = mu;
            stat[r][1] = ss / 128.f - mu * mu;
        }
    }
    __syncthreads();
    #pragma unroll
    for (int r = 0; r < 8; r++) {
        float mu = stat[r][0], var = stat[r][1];
        float v = (h1[r][tid] - mu) * rsqrtf(var + 1e-5f) * gg[tid] + gbe[tid];
        h1[r][tid] = fmaxf(v, 0.f);
    }
    __syncthreads();
    {
        int j = tid & 63, rr = tid >> 6;
        for (int rp = 0; rp < 4; rp++) {
            int r = rp * 2 + rr;
            float a = gb2[j];
            for (int i = 0; i < 128; i++) a = fmaf(h1[r][i], gW2[i * 64 + j], a);
            h2[r][j] = fmaxf(a, 0.f);
        }
    }
    __syncthreads();
    for (int r = wid * 2; r < wid * 2 + 2; r++) {
        float a = h2[r][lane] * gW3[lane] + h2[r][lane + 32] * gW3[lane + 32];
        #pragma unroll
        for (int o = 16; o >= 1; o >>= 1) a += __shfl_xor_sync(0xffffffffu, a, o);
        if (lane == 0) gsc[r] = 1.f / (1.f + expf(-(a + gb3[0])));
    }
    __syncthreads();

    if (tid < 64) {
        float acc[8];
        float bvv = cb1[tid];
        #pragma unroll
        for (int r = 0; r < 8; r++) acc[r] = bvv;
        for (int e = 0; e < EMB; e++) {
            float w = cW1[e * 64 + tid];
            #pragma unroll
            for (int r = 0; r < 8; r++) acc[r] = fmaf(xs[r][e], w, acc[r]);
        }
        #pragma unroll
        for (int r = 0; r < 8; r++) h1c[r][tid] = acc[r];
    }
    __syncthreads();
    for (int r = wid * 2; r < wid * 2 + 2; r++) {
        float v0 = h1c[r][lane], v1 = h1c[r][lane + 32];
        float s = v0 + v1;
        float ss = v0 * v0 + v1 * v1;
        #pragma unroll
        for (int o = 16; o >= 1; o >>= 1) {
            s  += __shfl_xor_sync(0xffffffffu, s, o);
            ss += __shfl_xor_sync(0xffffffffu, ss, o);
        }
        if (lane == 0) {
            float mu = s / 64.f;
            stat[r][0] = mu;
            stat[r][1] = ss / 64.f - mu * mu;
        }
    }
    __syncthreads();
    if (tid < 64) {
        #pragma unroll
        for (int r = 0; r < 8; r++) {
            float mu = stat[r][0], var = stat[r][1];
            float v = (h1c[r][tid] - mu) * rsqrtf(var + 1e-5f) * cg[tid] + cbe[tid];
            h1c[r][tid] = fmaxf(v, 0.f);
        }
    }
    __syncthreads();
    {
        int j = tid & 31, rr = tid >> 5;
        for (int rp = 0; rp < 2; rp++) {
            int r = rp * 4 + rr;
            float a = cb2[j];
            for (int i = 0; i < 64; i++) a = fmaf(h1c[r][i], cW2[i * 32 + j], a);
            h2c[r][j] = fmaxf(a, 0.f);
        }
    }
    __syncthreads();
    for (int r = wid * 2; r < wid * 2 + 2; r++) {
        float a = h2c[r][lane] * cW3[lane];
        #pragma unroll
        for (int o = 16; o >= 1; o >>= 1) a += __shfl_xor_sync(0xffffffffu, a, o);
        if (lane == 0) csc[r] = 1.f / (1.f + expf(-(a + cb3[0])));
    }
    __syncthreads();

    if (tid < 8) {
        int srow = (row0 + tid) & (SEQ - 1);
        float pos = 0.8f + 0.4f * (float)srow / 1023.f;
        float score = (0.7f * gsc[tid] + 0.3f * csc[tid]) * pos;
        int T = (int)ceilf(score * 20.f);
        T = min(max(T, 1), TMAXS);
        g_T[row0 + tid] = T;
    }
}

// ===========================================================================
// Kernel B: QKV fp32x2 GEMM (BM=128, BN=128, BK=16, double-buffered,
// 8x8 per thread as 4 m-pairs x 8 n) + LIF spike-sum epilogue.
// fp32-exact: each f32x2 lane is an IEEE fp32 FMA, sequential k-order.
// grid (EMB/128, MROWS/128, 3), 256 threads.
// ===========================================================================
#define GM_PAD 132

__global__ __launch_bounds__(256, 2) void qkv_kernel(
    const float* __restrict__ x,
    const float* __restrict__ Wq, const float* __restrict__ Wk, const float* __restrict__ Wv,
    const float* __restrict__ aq, const float* __restrict__ bq,
    const float* __restrict__ ak_, const float* __restrict__ bk_,
    const float* __restrict__ av, const float* __restrict__ bv)
{
    __shared__ float As[2][16 * GM_PAD];
    __shared__ float Bs[2][16 * 128];

    const int z = blockIdx.z;
    const float* W = (z == 0) ? Wq : ((z == 1) ? Wk : Wv);
    __nv_bfloat16* out = (z == 0) ? g_qb : ((z == 1) ? g_kb : g_vb);
    const float alpha = ((z == 0) ? aq : ((z == 1) ? ak_ : av))[0];
    const float beta  = ((z == 0) ? bq : ((z == 1) ? bk_ : bv))[0];

    const int t = threadIdx.x;
    const int tx = t & 15, ty = t >> 4;
    const int bm = blockIdx.y * 128, bn = blockIdx.x * 128;
    const int am = t >> 1, ak = (t & 1) * 8;
    const int bk = t >> 4, bn8 = (t & 15) * 8;

    const float* Ag = x + (size_t)(bm + am) * EMB + ak;
    const float* Bg = W + (size_t)bk * EMB + bn + bn8;

    uint64_t accp[4][8];
    #pragma unroll
    for (int p = 0; p < 4; p++)
        #pragma unroll
        for (int j = 0; j < 8; j++) accp[p][j] = 0ull;

    float4 a0 = *(const float4*)(Ag);
    float4 a1 = *(const float4*)(Ag + 4);
    float4 b0 = *(const float4*)(Bg);
    float4 b1 = *(const float4*)(Bg + 4);

    As[0][(ak + 0) * GM_PAD + am] = a0.x;
    As[0][(ak + 1) * GM_PAD + am] = a0.y;
    As[0][(ak + 2) * GM_PAD + am] = a0.z;
    As[0][(ak + 3) * GM_PAD + am] = a0.w;
    As[0][(ak + 4) * GM_PAD + am] = a1.x;
    As[0][(ak + 5) * GM_PAD + am] = a1.y;
    As[0][(ak + 6) * GM_PAD + am] = a1.z;
    As[0][(ak + 7) * GM_PAD + am] = a1.w;
    *(float4*)&Bs[0][bk * 128 + bn8] = b0;
    *(float4*)&Bs[0][bk * 128 + bn8 + 4] = b1;
    __syncthreads();

    #pragma unroll 1
    for (int kt = 0; kt < EMB / 16; kt++) {
        const int cur = kt & 1, nxt = cur ^ 1;
        if (kt < EMB / 16 - 1) {
            a0 = *(const float4*)(Ag + (kt + 1) * 16);
            a1 = *(const float4*)(Ag + (kt + 1) * 16 + 4);
            b0 = *(const float4*)(Bg + (size_t)(kt + 1) * 16 * EMB);
            b1 = *(const float4*)(Bg + (size_t)(kt + 1) * 16 * EMB + 4);
        }
        #pragma unroll
        for (int k = 0; k < 16; k++) {
            ulonglong2 a01 = *(const ulonglong2*)&As[cur][k * GM_PAD + ty * 4];
            ulonglong2 a23 = *(const ulonglong2*)&As[cur][k * GM_PAD + 64 + ty * 4];
            float4 bf0 = *(const float4*)&Bs[cur][k * 128 + tx * 8];
            float4 bf1 = *(const float4*)&Bs[cur][k * 128 + tx * 8 + 4];
            uint64_t bd[8];
            bd[0] = dup2(bf0.x); bd[1] = dup2(bf0.y);
            bd[2] = dup2(bf0.z); bd[3] = dup2(bf0.w);
            bd[4] = dup2(bf1.x); bd[5] = dup2(bf1.y);
            bd[6] = dup2(bf1.z); bd[7] = dup2(bf1.w);
            #pragma unroll
            for (int j = 0; j < 8; j++) {
                fma2(accp[0][j], a01.x, bd[j]);
                fma2(accp[1][j], a01.y, bd[j]);
                fma2(accp[2][j], a23.x, bd[j]);
                fma2(accp[3][j], a23.y, bd[j]);
            }
        }
        if (kt < EMB / 16 - 1) {
            As[nxt][(ak + 0) * GM_PAD + am] = a0.x;
            As[nxt][(ak + 1) * GM_PAD + am] = a0.y;
            As[nxt][(ak + 2) * GM_PAD + am] = a0.z;
            As[nxt][(ak + 3) * GM_PAD + am] = a0.w;
            As[nxt][(ak + 4) * GM_PAD + am] = a1.x;
            As[nxt][(ak + 5) * GM_PAD + am] = a1.y;
            As[nxt][(ak + 6) * GM_PAD + am] = a1.z;
            As[nxt][(ak + 7) * GM_PAD + am] = a1.w;
            *(float4*)&Bs[nxt][bk * 128 + bn8] = b0;
            *(float4*)&Bs[nxt][bk * 128 + bn8 + 4] = b1;
        }
        __syncthreads();
    }

    // LIF epilogue per row (pairs: p<2 -> rows ty*4 + p*2 + half; p>=2 -> +64)
    #pragma unroll
    for (int p = 0; p < 4; p++) {
        #pragma unroll
        for (int half = 0; half < 2; half++) {
            const int mloc = (p < 2) ? (ty * 4 + p * 2 + half)
                                     : (64 + ty * 4 + (p - 2) * 2 + half);
            const int r = bm + mloc;
            const int T = g_T[r];
            float y[8];
            #pragma unroll
            for (int j = 0; j < 8; j++) {
                float lo, hi;
                unpack2(accp[p][j], lo, hi);
                y[j] = half ? hi : lo;
            }
            float iv[8], vv[8], sa[8];
            #pragma unroll
            for (int j = 0; j < 8; j++) { iv[j] = 0.f; vv[j] = 0.f; sa[j] = 0.f; }
            for (int tt = 0; tt < T; tt++) {
                #pragma unroll
                for (int j = 0; j < 8; j++) {
                    iv[j] = fmaf(alpha, iv[j], y[j]);
                    vv[j] = fmaf(beta, vv[j], iv[j]);
                    float sp = (vv[j] >= 1.f) ? 1.f : 0.f;
                    sa[j] += sp;
                    vv[j] *= (1.f - sp);
                }
            }
            uint4 o4;
            o4.x = pack_bf2(sa[0], sa[1]);
            o4.y = pack_bf2(sa[2], sa[3]);
            o4.z = pack_bf2(sa[4], sa[5]);
            o4.w = pack_bf2(sa[6], sa[7]);
            *(uint4*)(out + (size_t)r * EMB + bn + tx * 8) = o4;
        }
    }
}

// ===========================================================================
// Kernel C: flash attention (warp bf16 MMA); epilogue emits 3-way bf16 split
// of the output (proj's pre-split A operand).
// ===========================================================================
#define KVPAD 72

__global__ __launch_bounds__(256) void attn_kernel()
{
    __shared__ __nv_bfloat16 sK[2][64 * KVPAD];
    __shared__ __nv_bfloat16 sV[2][64 * KVPAD];

    const int t = threadIdx.x;
    const int w = t >> 5, lane = t & 31;
    const int g = lane >> 2, tg = lane & 3;
    const int b = blockIdx.z, h = blockIdx.y;
    const int q0 = blockIdx.x * 128;
    const int qrow = q0 + w * 16;

    uint32_t qa[4][4];
    {
        const __nv_bfloat16* Qg = g_qb + (size_t)(b * SEQ + qrow) * EMB + h * HD;
        #pragma unroll
        for (int kt = 0; kt < 4; kt++) {
            qa[kt][0] = *(const uint32_t*)(Qg + (size_t)g * EMB + kt * 16 + 2 * tg);
            qa[kt][1] = *(const uint32_t*)(Qg + (size_t)(g + 8) * EMB + kt * 16 + 2 * tg);
            qa[kt][2] = *(const uint32_t*)(Qg + (size_t)g * EMB + kt * 16 + 8 + 2 * tg);
            qa[kt][3] = *(const uint32_t*)(Qg + (size_t)(g + 8) * EMB + kt * 16 + 8 + 2 * tg);
        }
    }

    const uint32_t kRowOff = (uint32_t)(lane & 7) * KVPAD + ((lane >> 3) & 1) * 8;
    const uint32_t vRowOff = (uint32_t)(lane & 15) * KVPAD;

    const __nv_bfloat16* Kg = g_kb + (size_t)(b * SEQ) * EMB + h * HD;
    const __nv_bfloat16* Vg = g_vb + (size_t)(b * SEQ) * EMB + h * HD;
    const int ldrow = t >> 2, ldsg = t & 3;

    {
        const __nv_bfloat16* kg = Kg + (size_t)ldrow * EMB;
        const __nv_bfloat16* vg = Vg + (size_t)ldrow * EMB;
        uint32_t ks = smem_u32(&sK[0][ldrow * KVPAD]);
        uint32_t vs = smem_u32(&sV[0][ldrow * KVPAD]);
        CP_ASYNC16(ks + ldsg * 16, kg + ldsg * 8);
        CP_ASYNC16(ks + (ldsg + 4) * 16, kg + (ldsg + 4) * 8);
        CP_ASYNC16(vs + ldsg * 16, vg + ldsg * 8);
        CP_ASYNC16(vs + (ldsg + 4) * 16, vg + (ldsg + 4) * 8);
        CP_COMMIT();
    }

    float o[8][4];
    #pragma unroll
    for (int nt = 0; nt < 8; nt++)
        #pragma unroll
        for (int i = 0; i < 4; i++) o[nt][i] = 0.f;
    float mA = -1e30f, mB = -1e30f, lA = 0.f, lB = 0.f;

    #pragma unroll 1
    for (int j = 0; j < 16; j++) {
        const int buf = j & 1;

        if (j < 15) {
            const int j1 = (j + 1) * 64;
            const __nv_bfloat16* kg = Kg + (size_t)(j1 + ldrow) * EMB;
            const __nv_bfloat16* vg = Vg + (size_t)(j1 + ldrow) * EMB;
            uint32_t ks = smem_u32(&sK[buf ^ 1][ldrow * KVPAD]);
            uint32_t vs = smem_u32(&sV[buf ^ 1][ldrow * KVPAD]);
            CP_ASYNC16(ks + ldsg * 16, kg + ldsg * 8);
            CP_ASYNC16(ks + (ldsg + 4) * 16, kg + (ldsg + 4) * 8);
            CP_ASYNC16(vs + ldsg * 16, vg + ldsg * 8);
            CP_ASYNC16(vs + (ldsg + 4) * 16, vg + (ldsg + 4) * 8);
            CP_COMMIT();
            CP_WAIT(1);
        } else {
            CP_WAIT(0);
        }
        __syncthreads();

        float s[8][4];
        const uint32_t kb = smem_u32(&sK[buf][0]);
        #pragma unroll
        for (int nt = 0; nt < 8; nt++) {
            #pragma unroll
            for (int i = 0; i < 4; i++) s[nt][i] = 0.f;
            #pragma unroll
            for (int kt = 0; kt < 4; kt++) {
                uint32_t k0, k1;
                LDMATRIX_X2(k0, k1, kb + (uint32_t)(nt * 8 * KVPAD + kt * 16) * 2 + kRowOff * 2);
                MMA_BF16(s[nt], qa[kt], k0, k1);
            }
        }

        float mxA = -1e30f, mxB = -1e30f;
        #pragma unroll
        for (int nt = 0; nt < 8; nt++) {
            s[nt][0] *= 0.125f; s[nt][1] *= 0.125f;
            s[nt][2] *= 0.125f; s[nt][3] *= 0.125f;
            mxA = fmaxf(mxA, fmaxf(s[nt][0], s[nt][1]));
            mxB = fmaxf(mxB, fmaxf(s[nt][2], s[nt][3]));
        }
        mxA = fmaxf(mxA, __shfl_xor_sync(0xffffffffu, mxA, 1));
        mxA = fmaxf(mxA, __shfl_xor_sync(0xffffffffu, mxA, 2));
        mxB = fmaxf(mxB, __shfl_xor_sync(0xffffffffu, mxB, 1));
        mxB = fmaxf(mxB, __shfl_xor_sync(0xffffffffu, mxB, 2));

        const float mnA = fmaxf(mA, mxA), mnB = fmaxf(mB, mxB);
        const float facA = __expf(mA - mnA), facB = __expf(mB - mnB);
        mA = mnA; mB = mnB;

        float sumA = 0.f, sumB = 0.f;
        #pragma unroll
        for (int nt = 0; nt < 8; nt++) {
            s[nt][0] = __expf(s[nt][0] - mnA);
            s[nt][1] = __expf(s[nt][1] - mnA);
            s[nt][2] = __expf(s[nt][2] - mnB);
            s[nt][3] = __expf(s[nt][3] - mnB);
            sumA += s[nt][0] + s[nt][1];
            sumB += s[nt][2] + s[nt][3];
        }
        sumA += __shfl_xor_sync(0xffffffffu, sumA, 1);
        sumA += __shfl_xor_sync(0xffffffffu, sumA, 2);
        sumB += __shfl_xor_sync(0xffffffffu, sumB, 1);
        sumB += __shfl_xor_sync(0xffffffffu, sumB, 2);
        lA = lA * facA + sumA;
        lB = lB * facB + sumB;

        #pragma unroll
        for (int nt = 0; nt < 8; nt++) {
            o[nt][0] *= facA; o[nt][1] *= facA;
            o[nt][2] *= facB; o[nt][3] *= facB;
        }

        uint32_t phi[4][4], plo[4][4];
        #pragma unroll
        for (int kt2 = 0; kt2 < 4; kt2++) {
            const int n0 = 2 * kt2, n1 = 2 * kt2 + 1;
            float p00 = s[n0][0], p01 = s[n0][1], p02 = s[n0][2], p03 = s[n0][3];
            float p10 = s[n1][0], p11 = s[n1][1], p12 = s[n1][2], p13 = s[n1][3];
            uint32_t h00 = pack_bf2(p00, p01), h01 = pack_bf2(p02, p03);
            uint32_t h10 = pack_bf2(p10, p11), h11 = pack_bf2(p12, p13);
            phi[kt2][0] = h00; phi[kt2][1] = h01; phi[kt2][2] = h10; phi[kt2][3] = h11;
            __nv_bfloat162 b00 = *(__nv_bfloat162*)&h00, b01 = *(__nv_bfloat162*)&h01;
            __nv_bfloat162 b10 = *(__nv_bfloat162*)&h10, b11 = *(__nv_bfloat162*)&h11;
            plo[kt2][0] = pack_bf2(p00 - __bfloat162float(b00.x), p01 - __bfloat162float(b00.y));
            plo[kt2][1] = pack_bf2(p02 - __bfloat162float(b01.x), p03 - __bfloat162float(b01.y));
            plo[kt2][2] = pack_bf2(p10 - __bfloat162float(b10.x), p11 - __bfloat162float(b10.y));
            plo[kt2][3] = pack_bf2(p12 - __bfloat162float(b11.x), p13 - __bfloat162float(b11.y));
        }

        const uint32_t vb = smem_u32(&sV[buf][0]);
        #pragma unroll
        for (int kt2 = 0; kt2 < 4; kt2++) {
            #pragma unroll
            for (int nt = 0; nt < 8; nt++) {
                uint32_t v0, v1;
                LDMATRIX_X2_T(v0, v1, vb + (uint32_t)(kt2 * 16 * KVPAD + nt * 8) * 2 + vRowOff * 2);
                MMA_BF16(o[nt], phi[kt2], v0, v1);
                MMA_BF16(o[nt], plo[kt2], v0, v1);
            }
        }
        __syncthreads();
    }

    // epilogue: normalize (fold v_mean = spikes/20), split 3-way for proj
    {
        const float invA = 1.f / (lA * 20.f), invB = 1.f / (lB * 20.f);
        const size_t rA = (size_t)(b * SEQ + qrow + g) * EMB + h * HD;
        const size_t rB = (size_t)(b * SEQ + qrow + g + 8) * EMB + h * HD;
        #pragma unroll
        for (int nt = 0; nt < 8; nt++) {
            float vA0 = o[nt][0] * invA, vA1 = o[nt][1] * invA;
            float vB0 = o[nt][2] * invB, vB1 = o[nt][3] * invB;
            __nv_bfloat16 a0, a1, a2, b0, b1, b2;
            split3(vA0, a0, a1, a2);
            split3(vA1, b0, b1, b2);
            const size_t offA = rA + nt * 8 + 2 * tg;
            *(uint32_t*)(gA0 + offA) = pack2b(a0, b0);
            *(uint32_t*)(gA1 + offA) = pack2b(a1, b1);
            *(uint32_t*)(gA2 + offA) = pack2b(a2, b2);
            split3(vB0, a0, a1, a2);
            split3(vB1, b0, b1, b2);
            const size_t offB = rB + nt * 8 + 2 * tg;
            *(uint32_t*)(gA0 + offB) = pack2b(a0, b0);
            *(uint32_t*)(gA1 + offB) = pack2b(a1, b1);
            *(uint32_t*)(gA2 + offB) = pack2b(a2, b2);
        }
    }
}

// ===========================================================================
// bf16x3 tensor-core GEMM core (proj only; no threshold downstream).
// Kept products {00,01,10,11,02,20}; output error ~1e-6 relative.
// BM=128, BN=64, BK=16, cp.async double-buffered; 8 warps 4x2, tile 32x32.
// ===========================================================================
#define AS_STRIDE 56   // bf16 units (112 bytes) per A row
#define BS_STRIDE 72   // bf16 units (144 bytes) per B row

__device__ __forceinline__ void stage_abk(
    const __nv_bfloat16* __restrict__ A0, const __nv_bfloat16* __restrict__ A1,
    const __nv_bfloat16* __restrict__ A2,
    const __nv_bfloat16* __restrict__ B0, const __nv_bfloat16* __restrict__ B1,
    const __nv_bfloat16* __restrict__ B2,
    __nv_bfloat16* sAbuf, __nv_bfloat16 (*sBbuf)[16 * BS_STRIDE],
    int k0, int t)
{
    const uint32_t abase = smem_u32(sAbuf);
    #pragma unroll
    for (int i = 0; i < 3; i++) {
        int c = i * 256 + t;
        int m = c / 6, rest = c - m * 6, tm = rest >> 1, half = rest & 1;
        const __nv_bfloat16* src =
            (tm == 0 ? A0 : (tm == 1 ? A1 : A2)) + (size_t)m * EMB + k0 + half * 8;
        CP_ASYNC16(abase + m * 112 + tm * 32 + half * 16, src);
    }
    {
        int c = t;
        int tm = c >> 7, rest = c & 127, k = rest >> 3, off = rest & 7;
        const __nv_bfloat16* src =
            (tm == 0 ? B0 : B1) + (size_t)(k0 + k) * EMB + off * 8;
        CP_ASYNC16(smem_u32(&sBbuf[tm][0]) + k * 144 + off * 16, src);
    }
    if (t < 128) {
        int rest = t, k = rest >> 3, off = rest & 7;
        const __nv_bfloat16* src = B2 + (size_t)(k0 + k) * EMB + off * 8;
        CP_ASYNC16(smem_u32(&sBbuf[2][0]) + k * 144 + off * 16, src);
    }
    CP_COMMIT();
}

__device__ __forceinline__ void bf16x3_core(
    const __nv_bfloat16* __restrict__ A0, const __nv_bfloat16* __restrict__ A1,
    const __nv_bfloat16* __restrict__ A2,
    const __nv_bfloat16* __restrict__ B0, const __nv_bfloat16* __restrict__ B1,
    const __nv_bfloat16* __restrict__ B2,
    __nv_bfloat16 sA[2][128 * AS_STRIDE],
    __nv_bfloat16 sB[2][3][16 * BS_STRIDE],
    float c[2][4][4], int t)
{
    const int lane = t & 31;
    const int w = t >> 5;
    const int wm = (w & 3) * 32, wn = (w >> 2) * 32;

    stage_abk(A0, A1, A2, B0, B1, B2, sA[0], sB[0], 0, t);

    #pragma unroll 1
    for (int j = 0; j < EMB / 16; j++) {
        const int buf = j & 1;
        if (j < EMB / 16 - 1) {
            stage_abk(A0, A1, A2, B0, B1, B2, sA[buf ^ 1], sB[buf ^ 1], (j + 1) * 16, t);
            CP_WAIT(1);
        } else {
            CP_WAIT(0);
        }
        __syncthreads();

        uint32_t a[3][2][4];
        const uint32_t abase = smem_u32(&sA[buf][0]);
        #pragma unroll
        for (int tm = 0; tm < 3; tm++)
            #pragma unroll
            for (int mi = 0; mi < 2; mi++) {
                uint32_t addr = abase +
                    ((uint32_t)(wm + mi * 16 + (lane & 15)) * AS_STRIDE + tm * 16 +
                     (lane >> 4) * 8) * 2;
                LDMATRIX_X4(a[tm][mi][0], a[tm][mi][1], a[tm][mi][2], a[tm][mi][3], addr);
            }
        uint32_t bfr[3][4][2];
        #pragma unroll
        for (int tm = 0; tm < 3; tm++) {
            const uint32_t bbase = smem_u32(&sB[buf][tm][0]);
            #pragma unroll
            for (int nt = 0; nt < 4; nt++) {
                uint32_t addr = bbase + ((uint32_t)(lane & 15) * BS_STRIDE + wn + nt * 8) * 2;
                LDMATRIX_X2_T(bfr[tm][nt][0], bfr[tm][nt][1], addr);
            }
        }
        #pragma unroll
        for (int mi = 0; mi < 2; mi++)
            #pragma unroll
            for (int nt = 0; nt < 4; nt++) {
                MMA_BF16(c[mi][nt], a[0][mi], bfr[0][nt][0], bfr[0][nt][1]);
                MMA_BF16(c[mi][nt], a[0][mi], bfr[1][nt][0], bfr[1][nt][1]);
                MMA_BF16(c[mi][nt], a[1][mi], bfr[0][nt][0], bfr[0][nt][1]);
                MMA_BF16(c[mi][nt], a[1][mi], bfr[1][nt][0], bfr[1][nt][1]);
                MMA_BF16(c[mi][nt], a[0][mi], bfr[2][nt][0], bfr[2][nt][1]);
                MMA_BF16(c[mi][nt], a[2][mi], bfr[0][nt][0], bfr[0][nt][1]);
            }
        __syncthreads();
    }
}

// ===========================================================================
// Kernel D: output projection (bf16x3)  out = attn @ Wo + bo
// grid (EMB/64, MROWS/128), 256 threads.
// ===========================================================================
__global__ __launch_bounds__(256, 2) void proj_kernel(
    const float* __restrict__ bo, float* __restrict__ out)
{
    __shared__ __nv_bfloat16 sA[2][128 * AS_STRIDE];
    __shared__ __nv_bfloat16 sB[2][3][16 * BS_STRIDE];

    const int t = threadIdx.x;
    const int w = t >> 5, lane = t & 31;
    const int wm = (w & 3) * 32, wn = (w >> 2) * 32;
    const int g = lane >> 2, tg = lane & 3;
    const int bm = blockIdx.y * 128, bn = blockIdx.x * 64;

    float c[2][4][4];
    #pragma unroll
    for (int mi = 0; mi < 2; mi++)
        #pragma unroll
        for (int ni = 0; ni < 4; ni++)
            #pragma unroll
            for (int i = 0; i < 4; i++) c[mi][ni][i] = 0.f;

    bf16x3_core(gA0 + (size_t)bm * EMB, gA1 + (size_t)bm * EMB, gA2 + (size_t)bm * EMB,
                gWo0 + bn, gWo1 + bn, gWo2 + bn,
                sA, sB, c, t);

    #pragma unroll
    for (int ni = 0; ni < 4; ni++) {
        const int cn = bn + wn + ni * 8 + tg * 2;
        const float b0v = bo[cn], b1v = bo[cn + 1];
        #pragma unroll
        for (int mi = 0; mi < 2; mi++) {
            const int r0 = bm + wm + mi * 16 + g;
            *(float2*)(out + (size_t)r0 * EMB + cn) =
                make_float2(c[mi][ni][0] + b0v, c[mi][ni][1] + b1v);
            *(float2*)(out + (size_t)(r0 + 8) * EMB + cn) =
                make_float2(c[mi][ni][2] + b0v, c[mi][ni][3] + b1v);
        }
    }
}

// ===========================================================================
extern "C" void kernel_launch(void* const* d_in, const int* in_sizes, int n_in,
                              void* d_out, int out_size)
{
    (void)in_sizes; (void)n_in; (void)out_size;
    const float* x   = (const float*)d_in[0];
    const float* Wq  = (const float*)d_in[1];
    const float* Wk  = (const float*)d_in[2];
    const float* Wv  = (const float*)d_in[3];
    const float* Wo  = (const float*)d_in[4];
    const float* bo  = (const float*)d_in[5];
    const float* gW1 = (const float*)d_in[6];
    const float* gb1 = (const float*)d_in[7];
    const float* gg  = (const float*)d_in[8];
    const float* gbe = (const float*)d_in[9];
    const float* gW2 = (const float*)d_in[10];
    const float* gb2 = (const float*)d_in[11];
    const float* gW3 = (const float*)d_in[12];
    const float* gb3 = (const float*)d_in[13];
    const float* cW1 = (const float*)d_in[14];
    const float* cb1 = (const float*)d_in[15];
    const float* cg  = (const float*)d_in[16];
    const float* cbe = (const float*)d_in[17];
    const float* cW2 = (const float*)d_in[18];
    const float* cb2 = (const float*)d_in[19];
    const float* cW3 = (const float*)d_in[20];
    const float* cb3 = (const float*)d_in[21];
    const float* aq  = (const float*)d_in[22];
    const float* bq  = (const float*)d_in[23];
    const float* ak  = (const float*)d_in[24];
    const float* bk  = (const float*)d_in[25];
    const float* av  = (const float*)d_in[26];
    const float* bv  = (const float*)d_in[27];
    float* out = (float*)d_out;

    split_wo_kernel<<<EMB * EMB / 1024, 256>>>(Wo);

    gate_kernel<<<MROWS / 8, 128>>>(x, gW1, gb1, gg, gbe, gW2, gb2, gW3, gb3,
                                    cW1, cb1, cg, cbe, cW2, cb2, cW3, cb3);

    qkv_kernel<<<dim3(EMB / 128, MROWS / 128, 3), 256>>>(x, Wq, Wk, Wv,
                                                         aq, bq, ak, bk, av, bv);

    attn_kernel<<<dim3(SEQ / 128, NH, BCNT), 256>>>();

    proj_kernel<<<dim3(EMB / 64, MROWS / 128), 256>>>(bo, out);
}

// round 14
// speedup vs baseline: 1.0267x; 1.0267x over previous
#include <cuda_runtime.h>
#include <cuda_bf16.h>
#include <math.h>
#include <stdint.h>

#define BCNT  4
#define SEQ   1024
#define EMB   512
#define NH    8
#define HD    64
#define MROWS 4096
#define TMAXS 20

// scratch (static device globals; allocation-free per harness rules)
__device__ __nv_bfloat16 g_qb[MROWS * EMB];   // spike counts (exact ints in bf16)
__device__ __nv_bfloat16 g_kb[MROWS * EMB];
__device__ __nv_bfloat16 g_vb[MROWS * EMB];   // RAW spike counts (no /20)
__device__ int   g_T[MROWS];

// 3-way bf16 splits for proj only (A = attention output, W = Wo)
__device__ __nv_bfloat16 gWo0[EMB * EMB], gWo1[EMB * EMB], gWo2[EMB * EMB];
__device__ __nv_bfloat16 gA0[MROWS * EMB], gA1[MROWS * EMB], gA2[MROWS * EMB];

// ===========================================================================
// PTX helpers (baseline PTX only)
// ===========================================================================
__device__ __forceinline__ uint32_t smem_u32(const void* p) {
    uint32_t a;
    asm("{ .reg .u64 t; cvta.to.shared.u64 t, %1; cvt.u32.u64 %0, t; }" : "=r"(a) : "l"(p));
    return a;
}

#define CP_ASYNC16(dst, src) \
    asm volatile("cp.async.cg.shared.global [%0], [%1], 16;" :: "r"(dst), "l"(src))
#define CP_COMMIT() asm volatile("cp.async.commit_group;" ::: "memory")
#define CP_WAIT(n)  asm volatile("cp.async.wait_group %0;" :: "n"(n) : "memory")

#define LDMATRIX_X2(r0, r1, addr) \
    asm volatile("ldmatrix.sync.aligned.m8n8.x2.shared.b16 {%0,%1}, [%2];" \
                 : "=r"(r0), "=r"(r1) : "r"(addr))
#define LDMATRIX_X2_T(r0, r1, addr) \
    asm volatile("ldmatrix.sync.aligned.m8n8.x2.trans.shared.b16 {%0,%1}, [%2];" \
                 : "=r"(r0), "=r"(r1) : "r"(addr))
#define LDMATRIX_X4(r0, r1, r2, r3, addr) \
    asm volatile("ldmatrix.sync.aligned.m8n8.x4.shared.b16 {%0,%1,%2,%3}, [%4];" \
                 : "=r"(r0), "=r"(r1), "=r"(r2), "=r"(r3) : "r"(addr))

#define MMA_BF16(d, a, b0, b1) \
    asm volatile("mma.sync.aligned.m16n8k16.row.col.f32.bf16.bf16.f32 " \
                 "{%0,%1,%2,%3}, {%4,%5,%6,%7}, {%8,%9}, {%0,%1,%2,%3};" \
                 : "+f"((d)[0]), "+f"((d)[1]), "+f"((d)[2]), "+f"((d)[3]) \
                 : "r"((a)[0]), "r"((a)[1]), "r"((a)[2]), "r"((a)[3]), \
                   "r"(b0), "r"(b1))

__device__ __forceinline__ uint32_t pack_bf2(float lo, float hi) {
    __nv_bfloat162 v = __floats2bfloat162_rn(lo, hi);
    return *(uint32_t*)&v;
}
__device__ __forceinline__ uint32_t pack2b(__nv_bfloat16 a, __nv_bfloat16 b) {
    return ((uint32_t)__bfloat16_as_ushort(b) << 16) | (uint32_t)__bfloat16_as_ushort(a);
}
__device__ __forceinline__ void split3(float v, __nv_bfloat16& b0, __nv_bfloat16& b1,
                                       __nv_bfloat16& b2) {
    b0 = __float2bfloat16(v);
    float r = v - __bfloat162float(b0);
    b1 = __float2bfloat16(r);
    float r2 = r - __bfloat162float(b1);
    b2 = __float2bfloat16(r2);
}

// packed fp32x2 FMA (each lane = IEEE fp32 fma.rn — fp32-exact semantics)
__device__ __forceinline__ void fma2(uint64_t& c, uint64_t a, uint64_t b) {
    asm("fma.rn.f32x2 %0, %1, %2, %0;" : "+l"(c) : "l"(a), "l"(b));
}
__device__ __forceinline__ uint64_t dup2(float x) {
    uint64_t r;
    asm("mov.b64 %0, {%1, %1};" : "=l"(r) : "f"(x));
    return r;
}
__device__ __forceinline__ void unpack2(uint64_t v, float& lo, float& hi) {
    asm("mov.b64 {%0, %1}, %2;" : "=f"(lo), "=f"(hi) : "l"(v));
}

// ===========================================================================
// split Wo (proj B operand) -> 3 bf16 terms
// ===========================================================================
__global__ __launch_bounds__(256) void split_wo_kernel(const float* __restrict__ Wo)
{
    const int base = (blockIdx.x * 256 + threadIdx.x) * 4;
    float4 v = *(const float4*)(Wo + base);
    __nv_bfloat16 a0, a1, a2, b0, b1, b2, c0, c1, c2, d0, d1, d2;
    split3(v.x, a0, a1, a2);
    split3(v.y, b0, b1, b2);
    split3(v.z, c0, c1, c2);
    split3(v.w, d0, d1, d2);
    *(uint2*)(gWo0 + base) = make_uint2(pack2b(a0, b0), pack2b(c0, d0));
    *(uint2*)(gWo1 + base) = make_uint2(pack2b(a1, b1), pack2b(c1, d1));
    *(uint2*)(gWo2 + base) = make_uint2(pack2b(a2, b2), pack2b(c2, d2));
}

// ===========================================================================
// Kernel A: gate + complexity MLPs -> adaptive window T_i (unchanged)
// ===========================================================================
__global__ __launch_bounds__(128) void gate_kernel(
    const float* __restrict__ x,
    const float* __restrict__ gW1, const float* __restrict__ gb1,
    const float* __restrict__ gg,  const float* __restrict__ gbe,
    const float* __restrict__ gW2, const float* __restrict__ gb2,
    const float* __restrict__ gW3, const float* __restrict__ gb3,
    const float* __restrict__ cW1, const float* __restrict__ cb1,
    const float* __restrict__ cg,  const float* __restrict__ cbe,
    const float* __restrict__ cW2, const float* __restrict__ cb2,
    const float* __restrict__ cW3, const float* __restrict__ cb3)
{
    __shared__ float xs[8][EMB];
    __shared__ float h1[8][128];
    __shared__ float h2[8][64];
    __shared__ float h1c[8][64];
    __shared__ float h2c[8][32];
    __shared__ float stat[8][2];
    __shared__ float gsc[8], csc[8];

    const int tid  = threadIdx.x;
    const int wid  = tid >> 5, lane = tid & 31;
    const int row0 = blockIdx.x * 8;

    for (int i = tid; i < 8 * EMB; i += 128)
        xs[i >> 9][i & 511] = x[row0 * EMB + i];
    __syncthreads();

    {
        float acc[8];
        float bvv = gb1[tid];
        #pragma unroll
        for (int r = 0; r < 8; r++) acc[r] = bvv;
        for (int e = 0; e < EMB; e++) {
            float w = gW1[e * 128 + tid];
            #pragma unroll
            for (int r = 0; r < 8; r++) acc[r] = fmaf(xs[r][e], w, acc[r]);
        }
        #pragma unroll
        for (int r = 0; r < 8; r++) h1[r][tid] = acc[r];
    }
    __syncthreads();
    for (int r = wid * 2; r < wid * 2 + 2; r++) {
        float v0 = h1[r][lane], v1 = h1[r][lane + 32], v2 = h1[r][lane + 64], v3 = h1[r][lane + 96];
        float s = v0 + v1 + v2 + v3;
        float ss = v0 * v0 + v1 * v1 + v2 * v2 + v3 * v3;
        #pragma unroll
        for (int o = 16; o >= 1; o >>= 1) {
            s  += __shfl_xor_sync(0xffffffffu, s, o);
            ss += __shfl_xor_sync(0xffffffffu, ss, o);
        }
        if (lane == 0) {
            float mu = s / 128.f;
            stat[r][0] = mu;
            stat[r][1] = ss / 128.f - mu * mu;
        }
    }
    __syncthreads();
    #pragma unroll
    for (int r = 0; r < 8; r++) {
        float mu = stat[r][0], var = stat[r][1];
        float v = (h1[r][tid] - mu) * rsqrtf(var + 1e-5f) * gg[tid] + gbe[tid];
        h1[r][tid] = fmaxf(v, 0.f);
    }
    __syncthreads();
    {
        int j = tid & 63, rr = tid >> 6;
        for (int rp = 0; rp < 4; rp++) {
            int r = rp * 2 + rr;
            float a = gb2[j];
            for (int i = 0; i < 128; i++) a = fmaf(h1[r][i], gW2[i * 64 + j], a);
            h2[r][j] = fmaxf(a, 0.f);
        }
    }
    __syncthreads();
    for (int r = wid * 2; r < wid * 2 + 2; r++) {
        float a = h2[r][lane] * gW3[lane] + h2[r][lane + 32] * gW3[lane + 32];
        #pragma unroll
        for (int o = 16; o >= 1; o >>= 1) a += __shfl_xor_sync(0xffffffffu, a, o);
        if (lane == 0) gsc[r] = 1.f / (1.f + expf(-(a + gb3[0])));
    }
    __syncthreads();

    if (tid < 64) {
        float acc[8];
        float bvv = cb1[tid];
        #pragma unroll
        for (int r = 0; r < 8; r++) acc[r] = bvv;
        for (int e = 0; e < EMB; e++) {
            float w = cW1[e * 64 + tid];
            #pragma unroll
            for (int r = 0; r < 8; r++) acc[r] = fmaf(xs[r][e], w, acc[r]);
        }
        #pragma unroll
        for (int r = 0; r < 8; r++) h1c[r][tid] = acc[r];
    }
    __syncthreads();
    for (int r = wid * 2; r < wid * 2 + 2; r++) {
        float v0 = h1c[r][lane], v1 = h1c[r][lane + 32];
        float s = v0 + v1;
        float ss = v0 * v0 + v1 * v1;
        #pragma unroll
        for (int o = 16; o >= 1; o >>= 1) {
            s  += __shfl_xor_sync(0xffffffffu, s, o);
            ss += __shfl_xor_sync(0xffffffffu, ss, o);
        }
        if (lane == 0) {
            float mu = s / 64.f;
            stat[r][0] = mu;
            stat[r][1] = ss / 64.f - mu * mu;
        }
    }
    __syncthreads();
    if (tid < 64) {
        #pragma unroll
        for (int r = 0; r < 8; r++) {
            float mu = stat[r][0], var = stat[r][1];
            float v = (h1c[r][tid] - mu) * rsqrtf(var + 1e-5f) * cg[tid] + cbe[tid];
            h1c[r][tid] = fmaxf(v, 0.f);
        }
    }
    __syncthreads();
    {
        int j = tid & 31, rr = tid >> 5;
        for (int rp = 0; rp < 2; rp++) {
            int r = rp * 4 + rr;
            float a = cb2[j];
            for (int i = 0; i < 64; i++) a = fmaf(h1c[r][i], cW2[i * 32 + j], a);
            h2c[r][j] = fmaxf(a, 0.f);
        }
    }
    __syncthreads();
    for (int r = wid * 2; r < wid * 2 + 2; r++) {
        float a = h2c[r][lane] * cW3[lane];
        #pragma unroll
        for (int o = 16; o >= 1; o >>= 1) a += __shfl_xor_sync(0xffffffffu, a, o);
        if (lane == 0) csc[r] = 1.f / (1.f + expf(-(a + cb3[0])));
    }
    __syncthreads();

    if (tid < 8) {
        int srow = (row0 + tid) & (SEQ - 1);
        float pos = 0.8f + 0.4f * (float)srow / 1023.f;
        float score = (0.7f * gsc[tid] + 0.3f * csc[tid]) * pos;
        int T = (int)ceilf(score * 20.f);
        T = min(max(T, 1), TMAXS);
        g_T[row0 + tid] = T;
    }
}

// ===========================================================================
// Kernel B: QKV fp32x2 GEMM — R9's proven core (BM=128, BN=64, BK=16,
// double-buffered, conflict-free) + LIF spike-sum epilogue.
// fp32-exact: each f32x2 lane is an IEEE fp32 FMA, sequential k-order.
// grid (EMB/64, MROWS/128, 3), 256 threads.
// ===========================================================================
#define GM_PAD 132

__global__ __launch_bounds__(256, 2) void qkv_kernel(
    const float* __restrict__ x,
    const float* __restrict__ Wq, const float* __restrict__ Wk, const float* __restrict__ Wv,
    const float* __restrict__ aq, const float* __restrict__ bq,
    const float* __restrict__ ak_, const float* __restrict__ bk_,
    const float* __restrict__ av, const float* __restrict__ bv)
{
    __shared__ float As[2][16 * GM_PAD];
    __shared__ float Bs[2][16 * 64];

    const int z = blockIdx.z;
    const float* W = (z == 0) ? Wq : ((z == 1) ? Wk : Wv);
    __nv_bfloat16* out = (z == 0) ? g_qb : ((z == 1) ? g_kb : g_vb);
    const float alpha = ((z == 0) ? aq : ((z == 1) ? ak_ : av))[0];
    const float beta  = ((z == 0) ? bq : ((z == 1) ? bk_ : bv))[0];

    const int t = threadIdx.x;
    const int tx = t & 15, ty = t >> 4;
    const int bm = blockIdx.y * 128, bn = blockIdx.x * 64;
    const int am = t >> 1, ak = (t & 1) * 8;
    const int bk = t >> 4, bn4 = (t & 15) * 4;

    const float* Ag = x + (size_t)(bm + am) * EMB + ak;
    const float* Bg = W + (size_t)bk * EMB + bn + bn4;

    uint64_t accp[4][4];
    #pragma unroll
    for (int p = 0; p < 4; p++)
        #pragma unroll
        for (int j = 0; j < 4; j++) accp[p][j] = 0ull;

    float4 a0 = *(const float4*)(Ag);
    float4 a1 = *(const float4*)(Ag + 4);
    float4 b0 = *(const float4*)(Bg);

    As[0][(ak + 0) * GM_PAD + am] = a0.x;
    As[0][(ak + 1) * GM_PAD + am] = a0.y;
    As[0][(ak + 2) * GM_PAD + am] = a0.z;
    As[0][(ak + 3) * GM_PAD + am] = a0.w;
    As[0][(ak + 4) * GM_PAD + am] = a1.x;
    As[0][(ak + 5) * GM_PAD + am] = a1.y;
    As[0][(ak + 6) * GM_PAD + am] = a1.z;
    As[0][(ak + 7) * GM_PAD + am] = a1.w;
    *(float4*)&Bs[0][bk * 64 + bn4] = b0;
    __syncthreads();

    #pragma unroll 1
    for (int kt = 0; kt < EMB / 16; kt++) {
        const int cur = kt & 1, nxt = cur ^ 1;
        if (kt < EMB / 16 - 1) {
            a0 = *(const float4*)(Ag + (kt + 1) * 16);
            a1 = *(const float4*)(Ag + (kt + 1) * 16 + 4);
            b0 = *(const float4*)(Bg + (size_t)(kt + 1) * 16 * EMB);
        }
        #pragma unroll
        for (int k = 0; k < 16; k++) {
            uint64_t ap[4];
            ap[0] = *(const uint64_t*)&As[cur][k * GM_PAD + ty * 4];
            ap[1] = *(const uint64_t*)&As[cur][k * GM_PAD + ty * 4 + 2];
            ap[2] = *(const uint64_t*)&As[cur][k * GM_PAD + 64 + ty * 4];
            ap[3] = *(const uint64_t*)&As[cur][k * GM_PAD + 64 + ty * 4 + 2];
            float bf[4];
            *(float4*)(bf) = *(const float4*)&Bs[cur][k * 64 + tx * 4];
            uint64_t bd0 = dup2(bf[0]), bd1 = dup2(bf[1]);
            uint64_t bd2 = dup2(bf[2]), bd3 = dup2(bf[3]);
            #pragma unroll
            for (int p = 0; p < 4; p++) {
                fma2(accp[p][0], ap[p], bd0);
                fma2(accp[p][1], ap[p], bd1);
                fma2(accp[p][2], ap[p], bd2);
                fma2(accp[p][3], ap[p], bd3);
            }
        }
        if (kt < EMB / 16 - 1) {
            As[nxt][(ak + 0) * GM_PAD + am] = a0.x;
            As[nxt][(ak + 1) * GM_PAD + am] = a0.y;
            As[nxt][(ak + 2) * GM_PAD + am] = a0.z;
            As[nxt][(ak + 3) * GM_PAD + am] = a0.w;
            As[nxt][(ak + 4) * GM_PAD + am] = a1.x;
            As[nxt][(ak + 5) * GM_PAD + am] = a1.y;
            As[nxt][(ak + 6) * GM_PAD + am] = a1.z;
            As[nxt][(ak + 7) * GM_PAD + am] = a1.w;
            *(float4*)&Bs[nxt][bk * 64 + bn4] = b0;
        }
        __syncthreads();
    }

    // LIF epilogue per row
    #pragma unroll
    for (int p = 0; p < 4; p++) {
        #pragma unroll
        for (int half = 0; half < 2; half++) {
            const int mloc = (p < 2) ? (ty * 4 + p * 2 + half)
                                     : (64 + ty * 4 + (p - 2) * 2 + half);
            const int r = bm + mloc;
            const int T = g_T[r];
            float y[4];
            #pragma unroll
            for (int j = 0; j < 4; j++) {
                float lo, hi;
                unpack2(accp[p][j], lo, hi);
                y[j] = half ? hi : lo;
            }
            float iv[4], vv[4], sa[4];
            #pragma unroll
            for (int j = 0; j < 4; j++) { iv[j] = 0.f; vv[j] = 0.f; sa[j] = 0.f; }
            for (int tt = 0; tt < T; tt++) {
                #pragma unroll
                for (int j = 0; j < 4; j++) {
                    iv[j] = fmaf(alpha, iv[j], y[j]);
                    vv[j] = fmaf(beta, vv[j], iv[j]);
                    float sp = (vv[j] >= 1.f) ? 1.f : 0.f;
                    sa[j] += sp;
                    vv[j] *= (1.f - sp);
                }
            }
            __nv_bfloat162* o2 = (__nv_bfloat162*)(out + (size_t)r * EMB + bn + tx * 4);
            o2[0] = __nv_bfloat162(__float2bfloat16(sa[0]), __float2bfloat16(sa[1]));
            o2[1] = __nv_bfloat162(__float2bfloat16(sa[2]), __float2bfloat16(sa[3]));
        }
    }
}

// ===========================================================================
// Kernel C: flash attention (warp bf16 MMA); epilogue emits 3-way bf16 split
// of the output (proj's pre-split A operand).
// ===========================================================================
#define KVPAD 72

__global__ __launch_bounds__(256) void attn_kernel()
{
    __shared__ __nv_bfloat16 sK[2][64 * KVPAD];
    __shared__ __nv_bfloat16 sV[2][64 * KVPAD];

    const int t = threadIdx.x;
    const int w = t >> 5, lane = t & 31;
    const int g = lane >> 2, tg = lane & 3;
    const int b = blockIdx.z, h = blockIdx.y;
    const int q0 = blockIdx.x * 128;
    const int qrow = q0 + w * 16;

    uint32_t qa[4][4];
    {
        const __nv_bfloat16* Qg = g_qb + (size_t)(b * SEQ + qrow) * EMB + h * HD;
        #pragma unroll
        for (int kt = 0; kt < 4; kt++) {
            qa[kt][0] = *(const uint32_t*)(Qg + (size_t)g * EMB + kt * 16 + 2 * tg);
            qa[kt][1] = *(const uint32_t*)(Qg + (size_t)(g + 8) * EMB + kt * 16 + 2 * tg);
            qa[kt][2] = *(const uint32_t*)(Qg + (size_t)g * EMB + kt * 16 + 8 + 2 * tg);
            qa[kt][3] = *(const uint32_t*)(Qg + (size_t)(g + 8) * EMB + kt * 16 + 8 + 2 * tg);
        }
    }

    const uint32_t kRowOff = (uint32_t)(lane & 7) * KVPAD + ((lane >> 3) & 1) * 8;
    const uint32_t vRowOff = (uint32_t)(lane & 15) * KVPAD;

    const __nv_bfloat16* Kg = g_kb + (size_t)(b * SEQ) * EMB + h * HD;
    const __nv_bfloat16* Vg = g_vb + (size_t)(b * SEQ) * EMB + h * HD;
    const int ldrow = t >> 2, ldsg = t & 3;

    {
        const __nv_bfloat16* kg = Kg + (size_t)ldrow * EMB;
        const __nv_bfloat16* vg = Vg + (size_t)ldrow * EMB;
        uint32_t ks = smem_u32(&sK[0][ldrow * KVPAD]);
        uint32_t vs = smem_u32(&sV[0][ldrow * KVPAD]);
        CP_ASYNC16(ks + ldsg * 16, kg + ldsg * 8);
        CP_ASYNC16(ks + (ldsg + 4) * 16, kg + (ldsg + 4) * 8);
        CP_ASYNC16(vs + ldsg * 16, vg + ldsg * 8);
        CP_ASYNC16(vs + (ldsg + 4) * 16, vg + (ldsg + 4) * 8);
        CP_COMMIT();
    }

    float o[8][4];
    #pragma unroll
    for (int nt = 0; nt < 8; nt++)
        #pragma unroll
        for (int i = 0; i < 4; i++) o[nt][i] = 0.f;
    float mA = -1e30f, mB = -1e30f, lA = 0.f, lB = 0.f;

    #pragma unroll 1
    for (int j = 0; j < 16; j++) {
        const int buf = j & 1;

        if (j < 15) {
            const int j1 = (j + 1) * 64;
            const __nv_bfloat16* kg = Kg + (size_t)(j1 + ldrow) * EMB;
            const __nv_bfloat16* vg = Vg + (size_t)(j1 + ldrow) * EMB;
            uint32_t ks = smem_u32(&sK[buf ^ 1][ldrow * KVPAD]);
            uint32_t vs = smem_u32(&sV[buf ^ 1][ldrow * KVPAD]);
            CP_ASYNC16(ks + ldsg * 16, kg + ldsg * 8);
            CP_ASYNC16(ks + (ldsg + 4) * 16, kg + (ldsg + 4) * 8);
            CP_ASYNC16(vs + ldsg * 16, vg + ldsg * 8);
            CP_ASYNC16(vs + (ldsg + 4) * 16, vg + (ldsg + 4) * 8);
            CP_COMMIT();
            CP_WAIT(1);
        } else {
            CP_WAIT(0);
        }
        __syncthreads();

        float s[8][4];
        const uint32_t kb = smem_u32(&sK[buf][0]);
        #pragma unroll
        for (int nt = 0; nt < 8; nt++) {
            #pragma unroll
            for (int i = 0; i < 4; i++) s[nt][i] = 0.f;
            #pragma unroll
            for (int kt = 0; kt < 4; kt++) {
                uint32_t k0, k1;
                LDMATRIX_X2(k0, k1, kb + (uint32_t)(nt * 8 * KVPAD + kt * 16) * 2 + kRowOff * 2);
                MMA_BF16(s[nt], qa[kt], k0, k1);
            }
        }

        float mxA = -1e30f, mxB = -1e30f;
        #pragma unroll
        for (int nt = 0; nt < 8; nt++) {
            s[nt][0] *= 0.125f; s[nt][1] *= 0.125f;
            s[nt][2] *= 0.125f; s[nt][3] *= 0.125f;
            mxA = fmaxf(mxA, fmaxf(s[nt][0], s[nt][1]));
            mxB = fmaxf(mxB, fmaxf(s[nt][2], s[nt][3]));
        }
        mxA = fmaxf(mxA, __shfl_xor_sync(0xffffffffu, mxA, 1));
        mxA = fmaxf(mxA, __shfl_xor_sync(0xffffffffu, mxA, 2));
        mxB = fmaxf(mxB, __shfl_xor_sync(0xffffffffu, mxB, 1));
        mxB = fmaxf(mxB, __shfl_xor_sync(0xffffffffu, mxB, 2));

        const float mnA = fmaxf(mA, mxA), mnB = fmaxf(mB, mxB);
        const float facA = __expf(mA - mnA), facB = __expf(mB - mnB);
        mA = mnA; mB = mnB;

        float sumA = 0.f, sumB = 0.f;
        #pragma unroll
        for (int nt = 0; nt < 8; nt++) {
            s[nt][0] = __expf(s[nt][0] - mnA);
            s[nt][1] = __expf(s[nt][1] - mnA);
            s[nt][2] = __expf(s[nt][2] - mnB);
            s[nt][3] = __expf(s[nt][3] - mnB);
            sumA += s[nt][0] + s[nt][1];
            sumB += s[nt][2] + s[nt][3];
        }
        sumA += __shfl_xor_sync(0xffffffffu, sumA, 1);
        sumA += __shfl_xor_sync(0xffffffffu, sumA, 2);
        sumB += __shfl_xor_sync(0xffffffffu, sumB, 1);
        sumB += __shfl_xor_sync(0xffffffffu, sumB, 2);
        lA = lA * facA + sumA;
        lB = lB * facB + sumB;

        #pragma unroll
        for (int nt = 0; nt < 8; nt++) {
            o[nt][0] *= facA; o[nt][1] *= facA;
            o[nt][2] *= facB; o[nt][3] *= facB;
        }

        uint32_t phi[4][4], plo[4][4];
        #pragma unroll
        for (int kt2 = 0; kt2 < 4; kt2++) {
            const int n0 = 2 * kt2, n1 = 2 * kt2 + 1;
            float p00 = s[n0][0], p01 = s[n0][1], p02 = s[n0][2], p03 = s[n0][3];
            float p10 = s[n1][0], p11 = s[n1][1], p12 = s[n1][2], p13 = s[n1][3];
            uint32_t h00 = pack_bf2(p00, p01), h01 = pack_bf2(p02, p03);
            uint32_t h10 = pack_bf2(p10, p11), h11 = pack_bf2(p12, p13);
            phi[kt2][0] = h00; phi[kt2][1] = h01; phi[kt2][2] = h10; phi[kt2][3] = h11;
            __nv_bfloat162 b00 = *(__nv_bfloat162*)&h00, b01 = *(__nv_bfloat162*)&h01;
            __nv_bfloat162 b10 = *(__nv_bfloat162*)&h10, b11 = *(__nv_bfloat162*)&h11;
            plo[kt2][0] = pack_bf2(p00 - __bfloat162float(b00.x), p01 - __bfloat162float(b00.y));
            plo[kt2][1] = pack_bf2(p02 - __bfloat162float(b01.x), p03 - __bfloat162float(b01.y));
            plo[kt2][2] = pack_bf2(p10 - __bfloat162float(b10.x), p11 - __bfloat162float(b10.y));
            plo[kt2][3] = pack_bf2(p12 - __bfloat162float(b11.x), p13 - __bfloat162float(b11.y));
        }

        const uint32_t vb = smem_u32(&sV[buf][0]);
        #pragma unroll
        for (int kt2 = 0; kt2 < 4; kt2++) {
            #pragma unroll
            for (int nt = 0; nt < 8; nt++) {
                uint32_t v0, v1;
                LDMATRIX_X2_T(v0, v1, vb + (uint32_t)(kt2 * 16 * KVPAD + nt * 8) * 2 + vRowOff * 2);
                MMA_BF16(o[nt], phi[kt2], v0, v1);
                MMA_BF16(o[nt], plo[kt2], v0, v1);
            }
        }
        __syncthreads();
    }

    // epilogue: normalize (fold v_mean = spikes/20), split 3-way for proj
    {
        const float invA = 1.f / (lA * 20.f), invB = 1.f / (lB * 20.f);
        const size_t rA = (size_t)(b * SEQ + qrow + g) * EMB + h * HD;
        const size_t rB = (size_t)(b * SEQ + qrow + g + 8) * EMB + h * HD;
        #pragma unroll
        for (int nt = 0; nt < 8; nt++) {
            float vA0 = o[nt][0] * invA, vA1 = o[nt][1] * invA;
            float vB0 = o[nt][2] * invB, vB1 = o[nt][3] * invB;
            __nv_bfloat16 a0, a1, a2, b0, b1, b2;
            split3(vA0, a0, a1, a2);
            split3(vA1, b0, b1, b2);
            const size_t offA = rA + nt * 8 + 2 * tg;
            *(uint32_t*)(gA0 + offA) = pack2b(a0, b0);
            *(uint32_t*)(gA1 + offA) = pack2b(a1, b1);
            *(uint32_t*)(gA2 + offA) = pack2b(a2, b2);
            split3(vB0, a0, a1, a2);
            split3(vB1, b0, b1, b2);
            const size_t offB = rB + nt * 8 + 2 * tg;
            *(uint32_t*)(gA0 + offB) = pack2b(a0, b0);
            *(uint32_t*)(gA1 + offB) = pack2b(a1, b1);
            *(uint32_t*)(gA2 + offB) = pack2b(a2, b2);
        }
    }
}

// ===========================================================================
// bf16x3 tensor-core GEMM core (proj only; no threshold downstream).
// Kept products {00,01,10,11,02,20}; output error ~1e-6 relative.
// BM=128, BN=64, BK=16, cp.async double-buffered; 8 warps 4x2, tile 32x32.
// ===========================================================================
#define AS_STRIDE 56   // bf16 units (112 bytes) per A row
#define BS_STRIDE 72   // bf16 units (144 bytes) per B row

__device__ __forceinline__ void stage_abk(
    const __nv_bfloat16* __restrict__ A0, const __nv_bfloat16* __restrict__ A1,
    const __nv_bfloat16* __restrict__ A2,
    const __nv_bfloat16* __restrict__ B0, const __nv_bfloat16* __restrict__ B1,
    const __nv_bfloat16* __restrict__ B2,
    __nv_bfloat16* sAbuf, __nv_bfloat16 (*sBbuf)[16 * BS_STRIDE],
    int k0, int t)
{
    const uint32_t abase = smem_u32(sAbuf);
    #pragma unroll
    for (int i = 0; i < 3; i++) {
        int c = i * 256 + t;
        int m = c / 6, rest = c - m * 6, tm = rest >> 1, half = rest & 1;
        const __nv_bfloat16* src =
            (tm == 0 ? A0 : (tm == 1 ? A1 : A2)) + (size_t)m * EMB + k0 + half * 8;
        CP_ASYNC16(abase + m * 112 + tm * 32 + half * 16, src);
    }
    {
        int c = t;
        int tm = c >> 7, rest = c & 127, k = rest >> 3, off = rest & 7;
        const __nv_bfloat16* src =
            (tm == 0 ? B0 : B1) + (size_t)(k0 + k) * EMB + off * 8;
        CP_ASYNC16(smem_u32(&sBbuf[tm][0]) + k * 144 + off * 16, src);
    }
    if (t < 128) {
        int rest = t, k = rest >> 3, off = rest & 7;
        const __nv_bfloat16* src = B2 + (size_t)(k0 + k) * EMB + off * 8;
        CP_ASYNC16(smem_u32(&sBbuf[2][0]) + k * 144 + off * 16, src);
    }
    CP_COMMIT();
}

__device__ __forceinline__ void bf16x3_core(
    const __nv_bfloat16* __restrict__ A0, const __nv_bfloat16* __restrict__ A1,
    const __nv_bfloat16* __restrict__ A2,
    const __nv_bfloat16* __restrict__ B0, const __nv_bfloat16* __restrict__ B1,
    const __nv_bfloat16* __restrict__ B2,
    __nv_bfloat16 sA[2][128 * AS_STRIDE],
    __nv_bfloat16 sB[2][3][16 * BS_STRIDE],
    float c[2][4][4], int t)
{
    const int lane = t & 31;
    const int w = t >> 5;
    const int wm = (w & 3) * 32, wn = (w >> 2) * 32;

    stage_abk(A0, A1, A2, B0, B1, B2, sA[0], sB[0], 0, t);

    #pragma unroll 1
    for (int j = 0; j < EMB / 16; j++) {
        const int buf = j & 1;
        if (j < EMB / 16 - 1) {
            stage_abk(A0, A1, A2, B0, B1, B2, sA[buf ^ 1], sB[buf ^ 1], (j + 1) * 16, t);
            CP_WAIT(1);
        } else {
            CP_WAIT(0);
        }
        __syncthreads();

        uint32_t a[3][2][4];
        const uint32_t abase = smem_u32(&sA[buf][0]);
        #pragma unroll
        for (int tm = 0; tm < 3; tm++)
            #pragma unroll
            for (int mi = 0; mi < 2; mi++) {
                uint32_t addr = abase +
                    ((uint32_t)(wm + mi * 16 + (lane & 15)) * AS_STRIDE + tm * 16 +
                     (lane >> 4) * 8) * 2;
                LDMATRIX_X4(a[tm][mi][0], a[tm][mi][1], a[tm][mi][2], a[tm][mi][3], addr);
            }
        uint32_t bfr[3][4][2];
        #pragma unroll
        for (int tm = 0; tm < 3; tm++) {
            const uint32_t bbase = smem_u32(&sB[buf][tm][0]);
            #pragma unroll
            for (int nt = 0; nt < 4; nt++) {
                uint32_t addr = bbase + ((uint32_t)(lane & 15) * BS_STRIDE + wn + nt * 8) * 2;
                LDMATRIX_X2_T(bfr[tm][nt][0], bfr[tm][nt][1], addr);
            }
        }
        #pragma unroll
        for (int mi = 0; mi < 2; mi++)
            #pragma unroll
            for (int nt = 0; nt < 4; nt++) {
                MMA_BF16(c[mi][nt], a[0][mi], bfr[0][nt][0], bfr[0][nt][1]);
                MMA_BF16(c[mi][nt], a[0][mi], bfr[1][nt][0], bfr[1][nt][1]);
                MMA_BF16(c[mi][nt], a[1][mi], bfr[0][nt][0], bfr[0][nt][1]);
                MMA_BF16(c[mi][nt], a[1][mi], bfr[1][nt][0], bfr[1][nt][1]);
                MMA_BF16(c[mi][nt], a[0][mi], bfr[2][nt][0], bfr[2][nt][1]);
                MMA_BF16(c[mi][nt], a[2][mi], bfr[0][nt][0], bfr[0][nt][1]);
            }
        __syncthreads();
    }
}

// ===========================================================================
// Kernel D: output projection (bf16x3)  out = attn @ Wo + bo
// grid (EMB/64, MROWS/128), 256 threads.
// ===========================================================================
__global__ __launch_bounds__(256, 2) void proj_kernel(
    const float* __restrict__ bo, float* __restrict__ out)
{
    __shared__ __nv_bfloat16 sA[2][128 * AS_STRIDE];
    __shared__ __nv_bfloat16 sB[2][3][16 * BS_STRIDE];

    const int t = threadIdx.x;
    const int w = t >> 5, lane = t & 31;
    const int wm = (w & 3) * 32, wn = (w >> 2) * 32;
    const int g = lane >> 2, tg = lane & 3;
    const int bm = blockIdx.y * 128, bn = blockIdx.x * 64;

    float c[2][4][4];
    #pragma unroll
    for (int mi = 0; mi < 2; mi++)
        #pragma unroll
        for (int ni = 0; ni < 4; ni++)
            #pragma unroll
            for (int i = 0; i < 4; i++) c[mi][ni][i] = 0.f;

    bf16x3_core(gA0 + (size_t)bm * EMB, gA1 + (size_t)bm * EMB, gA2 + (size_t)bm * EMB,
                gWo0 + bn, gWo1 + bn, gWo2 + bn,
                sA, sB, c, t);

    #pragma unroll
    for (int ni = 0; ni < 4; ni++) {
        const int cn = bn + wn + ni * 8 + tg * 2;
        const float b0v = bo[cn], b1v = bo[cn + 1];
        #pragma unroll
        for (int mi = 0; mi < 2; mi++) {
            const int r0 = bm + wm + mi * 16 + g;
            *(float2*)(out + (size_t)r0 * EMB + cn) =
                make_float2(c[mi][ni][0] + b0v, c[mi][ni][1] + b1v);
            *(float2*)(out + (size_t)(r0 + 8) * EMB + cn) =
                make_float2(c[mi][ni][2] + b0v, c[mi][ni][3] + b1v);
        }
    }
}

// ===========================================================================
extern "C" void kernel_launch(void* const* d_in, const int* in_sizes, int n_in,
                              void* d_out, int out_size)
{
    (void)in_sizes; (void)n_in; (void)out_size;
    const float* x   = (const float*)d_in[0];
    const float* Wq  = (const float*)d_in[1];
    const float* Wk  = (const float*)d_in[2];
    const float* Wv  = (const float*)d_in[3];
    const float* Wo  = (const float*)d_in[4];
    const float* bo  = (const float*)d_in[5];
    const float* gW1 = (const float*)d_in[6];
    const float* gb1 = (const float*)d_in[7];
    const float* gg  = (const float*)d_in[8];
    const float* gbe = (const float*)d_in[9];
    const float* gW2 = (const float*)d_in[10];
    const float* gb2 = (const float*)d_in[11];
    const float* gW3 = (const float*)d_in[12];
    const float* gb3 = (const float*)d_in[13];
    const float* cW1 = (const float*)d_in[14];
    const float* cb1 = (const float*)d_in[15];
    const float* cg  = (const float*)d_in[16];
    const float* cbe = (const float*)d_in[17];
    const float* cW2 = (const float*)d_in[18];
    const float* cb2 = (const float*)d_in[19];
    const float* cW3 = (const float*)d_in[20];
    const float* cb3 = (const float*)d_in[21];
    const float* aq  = (const float*)d_in[22];
    const float* bq  = (const float*)d_in[23];
    const float* ak  = (const float*)d_in[24];
    const float* bk  = (const float*)d_in[25];
    const float* av  = (const float*)d_in[26];
    const float* bv  = (const float*)d_in[27];
    float* out = (float*)d_out;

    split_wo_kernel<<<EMB * EMB / 1024, 256>>>(Wo);

    gate_kernel<<<MROWS / 8, 128>>>(x, gW1, gb1, gg, gbe, gW2, gb2, gW3, gb3,
                                    cW1, cb1, cg, cbe, cW2, cb2, cW3, cb3);

    qkv_kernel<<<dim3(EMB / 64, MROWS / 128, 3), 256>>>(x, Wq, Wk, Wv,
                                                        aq, bq, ak, bk, av, bv);

    attn_kernel<<<dim3(SEQ / 128, NH, BCNT), 256>>>();

    proj_kernel<<<dim3(EMB / 64, MROWS / 128), 256>>>(bo, out);
}